// round 11
// baseline (speedup 1.0000x reference)
#include <cuda_runtime.h>
#include <float.h>
#include <math.h>

// Problem constants (fixed by setup_inputs)
#define NPTS 8192
#define KNN 16
#define GS 192
#define NCELLS (GS * GS)          // 36864
#define NT 1024                   // threads per block (32 warps/SM)
#define NWPB (NT / 32)
#define SMEM_KEYS_BYTES (NWPB * 32 * KNN * 8)   // 128 KB

#define FIXP 16777216.0           // 2^24

typedef unsigned long long u64;

// ---------------- scratch (static device globals; no dynamic allocation) ----
__device__ float    g_mx[NPTS], g_my[NPTS];
__device__ unsigned g_benc[4] = {0xFFFFFFFFu, 0u, 0xFFFFFFFFu, 0u};
__device__ int      g_counts[NCELLS], g_qcounts[NCELLS];
__device__ int      g_start[NCELLS + 1];
__device__ int      g_fill[NCELLS], g_qfill[NCELLS];
__device__ int      g_cellof[NPTS], g_qcell[NPTS];
__device__ float4   g_bpt[NPTS];                 // x, y, id_bits, 0
__device__ float2   g_qxy[NPTS];
__device__ int      g_qid[NPTS];
__device__ int      g_knn[NPTS * KNN];
__device__ long long g_accum;
__device__ int      g_qnext;
__device__ int      g_done;
__device__ volatile int g_bar_cnt;
__device__ volatile int g_bar_gen;

__device__ __forceinline__ unsigned encf(float f) {
    unsigned u = __float_as_uint(f);
    return (u & 0x80000000u) ? ~u : (u | 0x80000000u);
}
__device__ __forceinline__ float decf(unsigned u) {
    unsigned v = (u & 0x80000000u) ? (u ^ 0x80000000u) : ~u;
    return __uint_as_float(v);
}

// Grid-wide barrier. Safe: gridDim.x == SM count, 1 block per SM co-resident.
__device__ __forceinline__ void gbar() {
    __syncthreads();
    if (threadIdx.x == 0) {
        int gen = g_bar_gen;
        __threadfence();
        int old = atomicAdd((int*)&g_bar_cnt, 1);
        if (old == (int)gridDim.x - 1) {
            g_bar_cnt = 0;
            __threadfence();
            g_bar_gen = gen + 1;
        } else {
            while (g_bar_gen == gen) __nanosleep(32);
            __threadfence();
        }
    }
    __syncthreads();
}

// Exclusive scan of NCELLS ints by one NT-thread block (2-pass, 36/thread).
__device__ __forceinline__ void scanN(const int* __restrict__ cnt,
                                      int* __restrict__ outp,
                                      int* __restrict__ outp2,
                                      bool write_total) {
    __shared__ int wsum[NWPB];
    int t = threadIdx.x, lane = t & 31, w = t >> 5;
    const int4* c4 = (const int4*)cnt;
    const int PT = NCELLS / NT / 4;      // int4s per thread = 9
    int tot = 0;
#pragma unroll
    for (int j = 0; j < PT; j++) {
        int4 a = c4[t * PT + j];
        tot += a.x + a.y + a.z + a.w;
    }
    int x = tot;
#pragma unroll
    for (int o = 1; o < 32; o <<= 1) {
        int u = __shfl_up_sync(0xFFFFFFFFu, x, o);
        if (lane >= o) x += u;
    }
    if (lane == 31) wsum[w] = x;
    __syncthreads();
    if (w == 0) {
        int y = wsum[lane];
#pragma unroll
        for (int o = 1; o < 32; o <<= 1) {
            int u = __shfl_up_sync(0xFFFFFFFFu, y, o);
            if (lane >= o) y += u;
        }
        wsum[lane] = y;
    }
    __syncthreads();
    int run = x - tot + (w > 0 ? wsum[w - 1] : 0);
#pragma unroll
    for (int j = 0; j < PT; j++) {
        int4 a = c4[t * PT + j];
        int4 o;
        o.x = run; o.y = run + a.x; o.z = o.y + a.y; o.w = o.z + a.z;
        run = o.w + a.w;
        ((int4*)outp)[t * PT + j] = o;
        ((int4*)outp2)[t * PT + j] = o;
    }
    if (write_total && t == NT - 1) outp[NCELLS] = run;
}

// Warp-collective count of points in clamped square radius r around (cx,cy).
__device__ __forceinline__ int count_square(int qcx, int qcy, int r, int lane) {
    int xl = max(0, qcx - r), xr = min(GS - 1, qcx + r);
    int yl = max(0, qcy - r), yh = min(GS - 1, qcy + r);
    int c = 0;
    for (int y = yl + lane; y <= yh; y += 32)
        c += g_start[y * GS + xr + 1] - g_start[y * GS + xl];
    return __reduce_add_sync(0xFFFFFFFFu, c);
}

// ---------------- the single persistent kernel ------------------------------

__global__ void __launch_bounds__(NT, 1) k_all(const float* __restrict__ ch1,
                                               const float* __restrict__ ch2,
                                               const float* __restrict__ M1,
                                               const float* __restrict__ M2,
                                               float* __restrict__ out) {
    extern __shared__ u64 s_keys[];     // interleaved: [(w*KNN + s)*32 + lane]
    __shared__ float s_red[4 * NWPB];
    __shared__ float s_sum[NWPB];

    int b = blockIdx.x, t = threadIdx.x;
    int NBr = gridDim.x;
    int lane = t & 31, w = t >> 5;
    int g = b * NT + t;
    int s0 = (int)(((long long)b * NPTS) / NBr);
    int e0 = (int)(((long long)(b + 1) * NPTS) / NBr);

    // ===== Phase A: zero counts, reset scalars, poly map + bbox =============
    {
        const int NQ4 = NCELLS / 4;      // 9216
        if (g < NQ4) ((int4*)g_counts)[g] = make_int4(0, 0, 0, 0);
        else if (g < 2 * NQ4) ((int4*)g_qcounts)[g - NQ4] = make_int4(0, 0, 0, 0);
        if (g == 0) { g_accum = 0; g_qnext = 0; g_done = 0; }

        float m10 = M1[0], m11 = M1[1], m12 = M1[2], m13 = M1[3];
        float m20 = M2[0], m21 = M2[1], m22 = M2[2], m23 = M2[3];
        float mnx = FLT_MAX, mxx = -FLT_MAX, mny = FLT_MAX, mxy = -FLT_MAX;
        for (int i = s0 + t; i < e0; i += NT) {
            float2 c = ((const float2*)ch2)[i];
            float y1 = m10 + m11 * c.y + m12 * c.x + m13 * c.x * c.y;
            float y2 = m20 + m21 * c.y + m22 * c.x + m23 * c.x * c.y;
            g_mx[i] = y1; g_my[i] = y2;
            mnx = fminf(mnx, y1); mxx = fmaxf(mxx, y1);
            mny = fminf(mny, y2); mxy = fmaxf(mxy, y2);
        }
#pragma unroll
        for (int o = 16; o > 0; o >>= 1) {
            mnx = fminf(mnx, __shfl_xor_sync(0xFFFFFFFFu, mnx, o));
            mxx = fmaxf(mxx, __shfl_xor_sync(0xFFFFFFFFu, mxx, o));
            mny = fminf(mny, __shfl_xor_sync(0xFFFFFFFFu, mny, o));
            mxy = fmaxf(mxy, __shfl_xor_sync(0xFFFFFFFFu, mxy, o));
        }
        if (lane == 0) {
            s_red[w] = mnx; s_red[NWPB + w] = mxx;
            s_red[2 * NWPB + w] = mny; s_red[3 * NWPB + w] = mxy;
        }
        __syncthreads();
        if (w == 0) {
            float A = s_red[lane];
            float B = s_red[NWPB + lane];
            float C = s_red[2 * NWPB + lane];
            float D = s_red[3 * NWPB + lane];
#pragma unroll
            for (int o = 16; o > 0; o >>= 1) {
                A = fminf(A, __shfl_xor_sync(0xFFFFFFFFu, A, o));
                B = fmaxf(B, __shfl_xor_sync(0xFFFFFFFFu, B, o));
                C = fminf(C, __shfl_xor_sync(0xFFFFFFFFu, C, o));
                D = fmaxf(D, __shfl_xor_sync(0xFFFFFFFFu, D, o));
            }
            if (lane == 0) {
                atomicMin(&g_benc[0], encf(A));
                atomicMax(&g_benc[1], encf(B));
                atomicMin(&g_benc[2], encf(C));
                atomicMax(&g_benc[3], encf(D));
            }
        }
    }
    gbar();

    // ===== Phase B: bin points + queries ====================================
    float minx = decf(g_benc[0]), maxx = decf(g_benc[1]);
    float miny = decf(g_benc[2]), maxy = decf(g_benc[3]);
    float rxr = fmaxf(maxx - minx, 1e-20f);
    float ryr = fmaxf(maxy - miny, 1e-20f);
    float ivx = (float)GS / rxr, ivy = (float)GS / ryr;
    float hx = rxr / (float)GS, hy = ryr / (float)GS;

    for (int i = s0 + t; i < e0; i += NT) {
        int cx = min(GS - 1, max(0, (int)((g_mx[i] - minx) * ivx)));
        int cy = min(GS - 1, max(0, (int)((g_my[i] - miny) * ivy)));
        int c = cy * GS + cx;
        g_cellof[i] = c;
        atomicAdd(&g_counts[c], 1);
        float2 q = ((const float2*)ch1)[i];
        int qcx = min(GS - 1, max(0, (int)((q.x - minx) * ivx)));
        int qcy = min(GS - 1, max(0, (int)((q.y - miny) * ivy)));
        int qc = qcy * GS + qcx;
        g_qcell[i] = qc;
        atomicAdd(&g_qcounts[qc], 1);
    }
    gbar();

    // ===== Phase C: scans (blocks 0 and 1 in parallel) ======================
    if (b == 0) scanN(g_counts, g_start, g_fill, true);
    else if (b == 1) scanN(g_qcounts, g_qfill, g_qfill, false);
    gbar();

    // ===== Phase D: scatter into cell-sorted order ==========================
    for (int i = s0 + t; i < e0; i += NT) {
        int c = g_cellof[i];
        int p = atomicAdd(&g_fill[c], 1);
        g_bpt[p] = make_float4(g_mx[i], g_my[i], __int_as_float(i), 0.0f);
        int qc = g_qcell[i];
        int pq = atomicAdd(&g_qfill[qc], 1);
        g_qxy[pq] = ((const float2*)ch1)[i];
        g_qid[pq] = i;
    }
    gbar();

    // ===== Phase E: dynamic warp-per-query exact 16-NN ======================
    {
        for (;;) {
            int q;
            if (lane == 0) q = atomicAdd(&g_qnext, 1);
            q = __shfl_sync(0xFFFFFFFFu, q, 0);
            if (q >= NPTS) break;

            float2 Q = g_qxy[q];
            float qx = Q.x, qy = Q.y;
            int orig = g_qid[q];
            int qcx = min(GS - 1, max(0, (int)((qx - minx) * ivx)));
            int qcy = min(GS - 1, max(0, (int)((qy - miny) * ivy)));

            // ---- inline r0: lanes 0-15 count squares of radius lane+1.
            int cnt = 0;
            if (lane < 16) {
                int rr = lane + 1;
                int xl = max(0, qcx - rr), xr = min(GS - 1, qcx + rr);
                int yl = max(0, qcy - rr), yh = min(GS - 1, qcy + rr);
                for (int y = yl; y <= yh; ++y)
                    cnt += g_start[y * GS + xr + 1] - g_start[y * GS + xl];
            }
            unsigned ball = __ballot_sync(0xFFFFFFFFu, (lane < 16) && (cnt >= KNN));
            int r0;
            if (ball) {
                r0 = __ffs(ball);                // lane idx + 1 == radius
            } else {                             // sparse edge cell: expand
                int lo = 16, hi = 24;
                int c2 = count_square(qcx, qcy, hi, lane);
                while (c2 < KNN && hi < GS) {
                    lo = hi; hi = min(GS, hi + (hi >> 1));
                    c2 = count_square(qcx, qcy, hi, lane);
                }
                while (hi - lo > 1) {
                    int mid = (lo + hi) >> 1;
                    if (count_square(qcx, qcy, mid, lane) >= KNN) hi = mid;
                    else lo = mid;
                }
                r0 = hi;
            }

            // D2 = far-corner bound of the r0-square around the cell.
            float dxf = fmaxf(qx - (minx + (float)(qcx - r0) * hx),
                              (minx + (float)(qcx + r0 + 1) * hx) - qx) + 1e-4f;
            float dyf = fmaxf(qy - (miny + (float)(qcy - r0) * hy),
                              (miny + (float)(qcy + r0 + 1) * hy) - qy) + 1e-4f;
            float D2 = dxf * dxf + dyf * dyf;
            float Dr = sqrtf(D2);

            int by0 = max(0, (int)floorf((qy - Dr - miny) * ivy) - 1);
            int by1 = min(GS - 1, (int)floorf((qy + Dr - miny) * ivy) + 1);

            u64 keys[KNN];
#pragma unroll
            for (int s = 0; s < KNN; s++) keys[s] = 0xFFFFFFFFFFFFFFFFull;

            for (int ybase = by0; ybase <= by1; ybase += 32) {
                int y = ybase + lane;
                int rs = 0, len = 0;
                if (y <= by1) {
                    // disc-shaped span: row y only needs |px-qx| <= dxmax
                    float ylo = miny + (float)y * hy, yhi = ylo + hy;
                    float dye = fmaxf(0.0f, fmaxf(ylo - qy, qy - yhi));
                    dye = fmaxf(dye - 1e-4f, 0.0f);
                    float rem = D2 - dye * dye;
                    if (rem > 0.0f) {
                        float dxm = sqrtf(rem);
                        int x0 = max(0, (int)floorf((qx - dxm - minx) * ivx) - 1);
                        int x1 = min(GS - 1, (int)floorf((qx + dxm - minx) * ivx) + 1);
                        rs = g_start[y * GS + x0];
                        len = g_start[y * GS + x1 + 1] - rs;
                    }
                }
                int pre = len;
#pragma unroll
                for (int o = 1; o < 32; o <<= 1) {
                    int u = __shfl_up_sync(0xFFFFFFFFu, pre, o);
                    if (lane >= o) pre += u;
                }
                int T = __shfl_sync(0xFFFFFFFFu, pre, 31);
                int excl = pre - len;

                for (int base = 0; base < T; base += 32) {
                    int idx = base + lane;
                    bool act = idx < T;
                    // find row j = max{j : excl_j <= idx} via shfl binary search
                    int jlo = 0;
#pragma unroll
                    for (int s = 16; s > 0; s >>= 1) {
                        int jm = jlo + s;
                        int ev = __shfl_sync(0xFFFFFFFFu, excl, min(jm, 31));
                        if (jm <= 31 && ev <= idx) jlo = jm;
                    }
                    int rrs = __shfl_sync(0xFFFFFFFFu, rs, jlo);
                    int rex = __shfl_sync(0xFFFFFFFFu, excl, jlo);
                    if (act) {
                        int tt = rrs + (idx - rex);
                        float4 p = g_bpt[tt];
                        float dx = qx - p.x;
                        float dy = qy - p.y;
                        float d = __fadd_rn(__fmul_rn(dx, dx), __fmul_rn(dy, dy));
                        if (d <= D2) {
                            u64 key = ((u64)__float_as_uint(d) << 32) |
                                      (unsigned)__float_as_int(p.z);
                            if (key < keys[KNN - 1]) {
                                keys[KNN - 1] = key;
#pragma unroll
                                for (int s = KNN - 1; s > 0; --s) {
                                    if (keys[s] < keys[s - 1]) {
                                        u64 tk = keys[s];
                                        keys[s] = keys[s - 1];
                                        keys[s - 1] = tk;
                                    }
                                }
                            }
                        }
                    }
                }
            }

            // exact sorted warp merge: interleaved smem + 2xREDUX per round
#pragma unroll
            for (int s = 0; s < KNN; s++)
                s_keys[(w * KNN + s) * 32 + lane] = keys[s];
            int head = 0;
            u64 cur = keys[0];
#pragma unroll 1
            for (int k = 0; k < KNN; k++) {
                unsigned hi = (unsigned)(cur >> 32);
                unsigned m = __reduce_min_sync(0xFFFFFFFFu, hi);
                unsigned lov = (hi == m) ? (unsigned)cur : 0xFFFFFFFFu;
                unsigned ml = __reduce_min_sync(0xFFFFFFFFu, lov);
                if (lane == 0) g_knn[orig * KNN + k] = (int)ml;
                if (hi == m && (unsigned)cur == ml) {
                    head++;
                    cur = (head < KNN) ? s_keys[(w * KNN + head) * 32 + lane]
                                       : 0xFFFFFFFFFFFFFFFFull;
                }
            }
        }
    }
    gbar();

    // ===== Phase F: scrambled gather + KL log-sum + last-block finale =======
    {
        float part = 0.0f;
        for (int n = s0 + t; n < e0; n += NT) {
            float2 qp = ((const float2*)ch1)[n];
            float qx = qp.x, qy = qp.y;
            int qq = n >> 4, col = n & 15;
            const float inv_s4 = 1.0f / 2.25f;  // 1 / sigma2^2, sigma2 = 1.5
            float acc = 0.0f;
#pragma unroll
            for (int k = 0; k < 16; k++) {
                int sel = g_knn[(k * 512 + qq) * KNN + col];
                float dx = qx - g_mx[sel];
                float dy = qy - g_my[sel];
                float D = 0.5f * (__fmul_rn(dx, dx) * inv_s4 + __fmul_rn(dy, dy) * inv_s4);
                acc += expf(-D);
            }
            float expD = acc * (1.0f / (float)NPTS);
            part += (expD != 0.0f) ? logf(expD) : 0.0f;
        }
#pragma unroll
        for (int o = 16; o > 0; o >>= 1)
            part += __shfl_xor_sync(0xFFFFFFFFu, part, o);
        if (lane == 0) s_sum[w] = part;
        __syncthreads();
        if (w == 0) {
            float v = s_sum[lane];
#pragma unroll
            for (int o = 16; o > 0; o >>= 1)
                v += __shfl_xor_sync(0xFFFFFFFFu, v, o);
            if (lane == 0) {
                long long fv = __double2ll_rn((double)v * FIXP);
                atomicAdd((unsigned long long*)&g_accum, (unsigned long long)fv);
                __threadfence();
                int old = atomicAdd(&g_done, 1);
                if (old == (int)gridDim.x - 1) {
                    u64 tot = atomicAdd((unsigned long long*)&g_accum, 0ull);
                    out[0] = (float)(-((double)(long long)tot / FIXP));
                }
            }
        }
    }
}

// ---------------- launch ----------------------------------------------------

extern "C" void kernel_launch(void* const* d_in, const int* in_sizes, int n_in,
                              void* d_out, int out_size) {
    (void)in_sizes; (void)n_in; (void)out_size;
    const float* ch1 = (const float*)d_in[0];
    const float* ch2 = (const float*)d_in[1];
    const float* M1  = (const float*)d_in[2];
    const float* M2  = (const float*)d_in[3];
    float* out = (float*)d_out;

    int dev = 0;
    cudaGetDevice(&dev);
    int sms = 0;
    cudaDeviceGetAttribute(&sms, cudaDevAttrMultiProcessorCount, dev);
    if (sms < 1 || sms > 1024) sms = 148;   // fail-safe

    cudaFuncSetAttribute(k_all, cudaFuncAttributeMaxDynamicSharedMemorySize,
                         SMEM_KEYS_BYTES);
    k_all<<<sms, NT, SMEM_KEYS_BYTES>>>(ch1, ch2, M1, M2, out);
}

// round 12
// speedup vs baseline: 1.4310x; 1.4310x over previous
#include <cuda_runtime.h>
#include <float.h>
#include <math.h>

// Problem constants (fixed by setup_inputs)
#define NPTS 8192
#define KNN 16
#define GS 192
#define NCELLS (GS * GS)          // 36864
#define NB 148                    // blocks (1 per SM, all co-resident)
#define NT 1024                   // threads per block (32 warps/SM)
#define NWPB (NT / 32)
#define NWARPS (NB * NWPB)
#define SMEM_KEYS_BYTES (NWPB * 32 * KNN * 8)   // 128 KB

#define FIXP 16777216.0           // 2^24

typedef unsigned long long u64;

// ---------------- scratch (static device globals; no dynamic allocation) ----
__device__ float    g_mx[NPTS], g_my[NPTS];
__device__ unsigned g_benc[4] = {0xFFFFFFFFu, 0u, 0xFFFFFFFFu, 0u};
__device__ int      g_counts[NCELLS], g_qcounts[NCELLS];
__device__ int      g_start[NCELLS + 1];
__device__ int      g_fill[NCELLS], g_qfill[NCELLS];
__device__ int      g_cellof[NPTS], g_qcell[NPTS];
__device__ float4   g_bpt[NPTS];                 // x, y, id_bits, 0
__device__ float2   g_qxy[NPTS];
__device__ int      g_qid[NPTS];
__device__ int      g_r0[NCELLS];                // per-query-cell square radius
__device__ int      g_knn[NPTS * KNN];
__device__ long long g_accum;
__device__ int      g_qnext;
__device__ volatile int g_bar_cnt;
__device__ volatile int g_bar_gen;

__device__ __forceinline__ unsigned encf(float f) {
    unsigned u = __float_as_uint(f);
    return (u & 0x80000000u) ? ~u : (u | 0x80000000u);
}
__device__ __forceinline__ float decf(unsigned u) {
    unsigned v = (u & 0x80000000u) ? (u ^ 0x80000000u) : ~u;
    return __uint_as_float(v);
}

// Grid-wide barrier. Safe: all NB blocks are co-resident (1 per SM).
__device__ __forceinline__ void gbar() {
    __syncthreads();
    if (threadIdx.x == 0) {
        int gen = g_bar_gen;
        __threadfence();
        int old = atomicAdd((int*)&g_bar_cnt, 1);
        if (old == NB - 1) {
            g_bar_cnt = 0;
            __threadfence();
            g_bar_gen = gen + 1;
        } else {
            while (g_bar_gen == gen) __nanosleep(32);
            __threadfence();
        }
    }
    __syncthreads();
}

// Exclusive scan of NCELLS ints by one NT-thread block (2-pass, 36/thread).
__device__ __forceinline__ void scanN(const int* __restrict__ cnt,
                                      int* __restrict__ outp,
                                      int* __restrict__ outp2,
                                      bool write_total) {
    __shared__ int wsum[NWPB];
    int t = threadIdx.x, lane = t & 31, w = t >> 5;
    const int4* c4 = (const int4*)cnt;
    const int PT = NCELLS / NT / 4;      // int4s per thread = 9
    int tot = 0;
#pragma unroll
    for (int j = 0; j < PT; j++) {
        int4 a = c4[t * PT + j];
        tot += a.x + a.y + a.z + a.w;
    }
    int x = tot;
#pragma unroll
    for (int o = 1; o < 32; o <<= 1) {
        int u = __shfl_up_sync(0xFFFFFFFFu, x, o);
        if (lane >= o) x += u;
    }
    if (lane == 31) wsum[w] = x;
    __syncthreads();
    if (w == 0) {
        int y = wsum[lane];
#pragma unroll
        for (int o = 1; o < 32; o <<= 1) {
            int u = __shfl_up_sync(0xFFFFFFFFu, y, o);
            if (lane >= o) y += u;
        }
        wsum[lane] = y;
    }
    __syncthreads();
    int run = x - tot + (w > 0 ? wsum[w - 1] : 0);
#pragma unroll
    for (int j = 0; j < PT; j++) {
        int4 a = c4[t * PT + j];
        int4 o;
        o.x = run; o.y = run + a.x; o.z = o.y + a.y; o.w = o.z + a.z;
        run = o.w + a.w;
        ((int4*)outp)[t * PT + j] = o;
        ((int4*)outp2)[t * PT + j] = o;
    }
    if (write_total && t == NT - 1) outp[NCELLS] = run;
}

// Warp-collective count of points in clamped square radius r around (cx,cy).
__device__ __forceinline__ int count_square(int qcx, int qcy, int r, int lane) {
    int xl = max(0, qcx - r), xr = min(GS - 1, qcx + r);
    int yl = max(0, qcy - r), yh = min(GS - 1, qcy + r);
    int c = 0;
    for (int y = yl + lane; y <= yh; y += 32)
        c += g_start[y * GS + xr + 1] - g_start[y * GS + xl];
    return __reduce_add_sync(0xFFFFFFFFu, c);
}

// ---------------- the single persistent kernel ------------------------------

__global__ void __launch_bounds__(NT, 1) k_all(const float* __restrict__ ch1,
                                               const float* __restrict__ ch2,
                                               const float* __restrict__ M1,
                                               const float* __restrict__ M2,
                                               float* __restrict__ out) {
    extern __shared__ u64 s_keys[];     // interleaved: [(w*KNN + s)*32 + lane]
    __shared__ float s_red[4 * NWPB];
    __shared__ float s_sum[NWPB];

    int b = blockIdx.x, t = threadIdx.x;
    int lane = t & 31, w = t >> 5;
    int g = b * NT + t;
    int s0 = (int)(((long long)b * NPTS) / NB);
    int e0 = (int)(((long long)(b + 1) * NPTS) / NB);

    // ===== Phase A: zero counts, reset scalars, poly map + bbox =============
    {
        const int NQ4 = NCELLS / 4;      // 9216
        if (g < NQ4) ((int4*)g_counts)[g] = make_int4(0, 0, 0, 0);
        else if (g < 2 * NQ4) ((int4*)g_qcounts)[g - NQ4] = make_int4(0, 0, 0, 0);
        if (g == 0) { g_accum = 0; g_qnext = 0; }

        float m10 = M1[0], m11 = M1[1], m12 = M1[2], m13 = M1[3];
        float m20 = M2[0], m21 = M2[1], m22 = M2[2], m23 = M2[3];
        float mnx = FLT_MAX, mxx = -FLT_MAX, mny = FLT_MAX, mxy = -FLT_MAX;
        for (int i = s0 + t; i < e0; i += NT) {
            float2 c = ((const float2*)ch2)[i];
            float y1 = m10 + m11 * c.y + m12 * c.x + m13 * c.x * c.y;
            float y2 = m20 + m21 * c.y + m22 * c.x + m23 * c.x * c.y;
            g_mx[i] = y1; g_my[i] = y2;
            mnx = fminf(mnx, y1); mxx = fmaxf(mxx, y1);
            mny = fminf(mny, y2); mxy = fmaxf(mxy, y2);
        }
#pragma unroll
        for (int o = 16; o > 0; o >>= 1) {
            mnx = fminf(mnx, __shfl_xor_sync(0xFFFFFFFFu, mnx, o));
            mxx = fmaxf(mxx, __shfl_xor_sync(0xFFFFFFFFu, mxx, o));
            mny = fminf(mny, __shfl_xor_sync(0xFFFFFFFFu, mny, o));
            mxy = fmaxf(mxy, __shfl_xor_sync(0xFFFFFFFFu, mxy, o));
        }
        if (lane == 0) {
            s_red[w] = mnx; s_red[NWPB + w] = mxx;
            s_red[2 * NWPB + w] = mny; s_red[3 * NWPB + w] = mxy;
        }
        __syncthreads();
        if (w == 0) {
            float A = s_red[lane];
            float B = s_red[NWPB + lane];
            float C = s_red[2 * NWPB + lane];
            float D = s_red[3 * NWPB + lane];
#pragma unroll
            for (int o = 16; o > 0; o >>= 1) {
                A = fminf(A, __shfl_xor_sync(0xFFFFFFFFu, A, o));
                B = fmaxf(B, __shfl_xor_sync(0xFFFFFFFFu, B, o));
                C = fminf(C, __shfl_xor_sync(0xFFFFFFFFu, C, o));
                D = fmaxf(D, __shfl_xor_sync(0xFFFFFFFFu, D, o));
            }
            if (lane == 0) {
                atomicMin(&g_benc[0], encf(A));
                atomicMax(&g_benc[1], encf(B));
                atomicMin(&g_benc[2], encf(C));
                atomicMax(&g_benc[3], encf(D));
            }
        }
    }
    gbar();

    // ===== Phase B: bin points + queries ====================================
    float minx = decf(g_benc[0]), maxx = decf(g_benc[1]);
    float miny = decf(g_benc[2]), maxy = decf(g_benc[3]);
    float rxr = fmaxf(maxx - minx, 1e-20f);
    float ryr = fmaxf(maxy - miny, 1e-20f);
    float ivx = (float)GS / rxr, ivy = (float)GS / ryr;
    float hx = rxr / (float)GS, hy = ryr / (float)GS;

    for (int i = s0 + t; i < e0; i += NT) {
        int cx = min(GS - 1, max(0, (int)((g_mx[i] - minx) * ivx)));
        int cy = min(GS - 1, max(0, (int)((g_my[i] - miny) * ivy)));
        int c = cy * GS + cx;
        g_cellof[i] = c;
        atomicAdd(&g_counts[c], 1);
        float2 q = ((const float2*)ch1)[i];
        int qcx = min(GS - 1, max(0, (int)((q.x - minx) * ivx)));
        int qcy = min(GS - 1, max(0, (int)((q.y - miny) * ivy)));
        int qc = qcy * GS + qcx;
        g_qcell[i] = qc;
        atomicAdd(&g_qcounts[qc], 1);
    }
    gbar();

    // ===== Phase C: scans (blocks 0 and 1 in parallel) ======================
    if (b == 0) scanN(g_counts, g_start, g_fill, true);
    else if (b == 1) scanN(g_qcounts, g_qfill, g_qfill, false);
    gbar();

    // ===== Phase D: scatter + per-cell r0 precompute ========================
    for (int i = s0 + t; i < e0; i += NT) {
        int c = g_cellof[i];
        int p = atomicAdd(&g_fill[c], 1);
        g_bpt[p] = make_float4(g_mx[i], g_my[i], __int_as_float(i), 0.0f);
        int qc = g_qcell[i];
        int pq = atomicAdd(&g_qfill[qc], 1);
        g_qxy[pq] = ((const float2*)ch1)[i];
        g_qid[pq] = i;
    }
    // E0: exact minimal r0 per occupied query cell, lanes 0-15 test r=1..16
    {
        int wg = b * NWPB + w;
        for (int cell = wg; cell < NCELLS; cell += NWARPS) {
            if (g_qcounts[cell] == 0) continue;
            int qcx = cell % GS, qcy = cell / GS;
            int cnt = 0;
            if (lane < 16) {
                int rr = lane + 1;
                int xl = max(0, qcx - rr), xr = min(GS - 1, qcx + rr);
                int yl = max(0, qcy - rr), yh = min(GS - 1, qcy + rr);
                for (int y = yl; y <= yh; ++y)
                    cnt += g_start[y * GS + xr + 1] - g_start[y * GS + xl];
            }
            unsigned ball = __ballot_sync(0xFFFFFFFFu, (lane < 16) && (cnt >= KNN));
            int r0v;
            if (ball) {
                r0v = __ffs(ball);               // lane idx + 1 == radius
            } else {                             // sparse edge cell: expand
                int lo = 16, hi = 24;
                int c2 = count_square(qcx, qcy, hi, lane);
                while (c2 < KNN && hi < GS) {
                    lo = hi; hi = min(GS, hi + (hi >> 1));
                    c2 = count_square(qcx, qcy, hi, lane);
                }
                while (hi - lo > 1) {
                    int mid = (lo + hi) >> 1;
                    if (count_square(qcx, qcy, mid, lane) >= KNN) hi = mid;
                    else lo = mid;
                }
                r0v = hi;
            }
            if (lane == 0) g_r0[cell] = r0v;
        }
    }
    gbar();

    // ===== Phase E: dynamic warp-per-query exact 16-NN ======================
    {
        for (;;) {
            int q;
            if (lane == 0) q = atomicAdd(&g_qnext, 1);
            q = __shfl_sync(0xFFFFFFFFu, q, 0);
            if (q >= NPTS) break;

            float2 Q = g_qxy[q];
            float qx = Q.x, qy = Q.y;
            int orig = g_qid[q];
            int qcx = min(GS - 1, max(0, (int)((qx - minx) * ivx)));
            int qcy = min(GS - 1, max(0, (int)((qy - miny) * ivy)));
            int r0 = g_r0[qcy * GS + qcx];

            // D2 = far-corner bound of the r0-square around the cell.
            float dxf = fmaxf(qx - (minx + (float)(qcx - r0) * hx),
                              (minx + (float)(qcx + r0 + 1) * hx) - qx) + 1e-4f;
            float dyf = fmaxf(qy - (miny + (float)(qcy - r0) * hy),
                              (miny + (float)(qcy + r0 + 1) * hy) - qy) + 1e-4f;
            float D2 = dxf * dxf + dyf * dyf;
            float Dr = sqrtf(D2);

            int by0 = max(0, (int)floorf((qy - Dr - miny) * ivy) - 1);
            int by1 = min(GS - 1, (int)floorf((qy + Dr - miny) * ivy) + 1);

            u64 keys[KNN];
#pragma unroll
            for (int s = 0; s < KNN; s++) keys[s] = 0xFFFFFFFFFFFFFFFFull;

            for (int ybase = by0; ybase <= by1; ybase += 32) {
                int y = ybase + lane;
                int rs = 0, len = 0;
                if (y <= by1) {
                    // disc-shaped span: row y only needs |px-qx| <= dxmax
                    float ylo = miny + (float)y * hy, yhi = ylo + hy;
                    float dye = fmaxf(0.0f, fmaxf(ylo - qy, qy - yhi));
                    dye = fmaxf(dye - 1e-4f, 0.0f);
                    float rem = D2 - dye * dye;
                    if (rem > 0.0f) {
                        float dxm = sqrtf(rem);
                        int x0 = max(0, (int)floorf((qx - dxm - minx) * ivx) - 1);
                        int x1 = min(GS - 1, (int)floorf((qx + dxm - minx) * ivx) + 1);
                        rs = g_start[y * GS + x0];
                        len = g_start[y * GS + x1 + 1] - rs;
                    }
                }
                int pre = len;
#pragma unroll
                for (int o = 1; o < 32; o <<= 1) {
                    int u = __shfl_up_sync(0xFFFFFFFFu, pre, o);
                    if (lane >= o) pre += u;
                }
                int T = __shfl_sync(0xFFFFFFFFu, pre, 31);
                int excl = pre - len;

                for (int base = 0; base < T; base += 32) {
                    int idx = base + lane;
                    bool act = idx < T;
                    // find row j = max{j : excl_j <= idx} via shfl binary search
                    int jlo = 0;
#pragma unroll
                    for (int s = 16; s > 0; s >>= 1) {
                        int jm = jlo + s;
                        int ev = __shfl_sync(0xFFFFFFFFu, excl, min(jm, 31));
                        if (jm <= 31 && ev <= idx) jlo = jm;
                    }
                    int rrs = __shfl_sync(0xFFFFFFFFu, rs, jlo);
                    int rex = __shfl_sync(0xFFFFFFFFu, excl, jlo);
                    if (act) {
                        int tt = rrs + (idx - rex);
                        float4 p = g_bpt[tt];
                        float dx = qx - p.x;
                        float dy = qy - p.y;
                        float d = __fadd_rn(__fmul_rn(dx, dx), __fmul_rn(dy, dy));
                        if (d <= D2) {
                            u64 key = ((u64)__float_as_uint(d) << 32) |
                                      (unsigned)__float_as_int(p.z);
                            if (key < keys[KNN - 1]) {
                                keys[KNN - 1] = key;
#pragma unroll
                                for (int s = KNN - 1; s > 0; --s) {
                                    if (keys[s] < keys[s - 1]) {
                                        u64 tk = keys[s];
                                        keys[s] = keys[s - 1];
                                        keys[s - 1] = tk;
                                    }
                                }
                            }
                        }
                    }
                }
            }

            // exact sorted warp merge: interleaved smem + 2xREDUX per round
#pragma unroll
            for (int s = 0; s < KNN; s++)
                s_keys[(w * KNN + s) * 32 + lane] = keys[s];
            int head = 0;
            u64 cur = keys[0];
#pragma unroll 1
            for (int k = 0; k < KNN; k++) {
                unsigned hi = (unsigned)(cur >> 32);
                unsigned m = __reduce_min_sync(0xFFFFFFFFu, hi);
                unsigned lov = (hi == m) ? (unsigned)cur : 0xFFFFFFFFu;
                unsigned ml = __reduce_min_sync(0xFFFFFFFFu, lov);
                if (lane == 0) g_knn[orig * KNN + k] = (int)ml;
                if (hi == m && (unsigned)cur == ml) {
                    head++;
                    cur = (head < KNN) ? s_keys[(w * KNN + head) * 32 + lane]
                                       : 0xFFFFFFFFFFFFFFFFull;
                }
            }
        }
    }
    gbar();

    // ===== Phase F: scrambled gather + KL log-sum ===========================
    {
        float part = 0.0f;
        for (int n = s0 + t; n < e0; n += NT) {
            float2 qp = ((const float2*)ch1)[n];
            float qx = qp.x, qy = qp.y;
            int qq = n >> 4, col = n & 15;
            const float inv_s4 = 1.0f / 2.25f;  // 1 / sigma2^2, sigma2 = 1.5
            float acc = 0.0f;
#pragma unroll
            for (int k = 0; k < 16; k++) {
                int sel = g_knn[(k * 512 + qq) * KNN + col];
                float dx = qx - g_mx[sel];
                float dy = qy - g_my[sel];
                float D = 0.5f * (__fmul_rn(dx, dx) * inv_s4 + __fmul_rn(dy, dy) * inv_s4);
                acc += expf(-D);
            }
            float expD = acc * (1.0f / (float)NPTS);
            part += (expD != 0.0f) ? logf(expD) : 0.0f;
        }
#pragma unroll
        for (int o = 16; o > 0; o >>= 1)
            part += __shfl_xor_sync(0xFFFFFFFFu, part, o);
        if (lane == 0) s_sum[w] = part;
        __syncthreads();
        if (w == 0) {
            float v = s_sum[lane];
#pragma unroll
            for (int o = 16; o > 0; o >>= 1)
                v += __shfl_xor_sync(0xFFFFFFFFu, v, o);
            if (lane == 0) {
                long long fv = __double2ll_rn((double)v * FIXP);
                atomicAdd((unsigned long long*)&g_accum, (unsigned long long)fv);
            }
        }
    }
    gbar();

    if (b == 0 && t == 0)
        out[0] = (float)(-((double)g_accum / FIXP));
}

// ---------------- launch ----------------------------------------------------

extern "C" void kernel_launch(void* const* d_in, const int* in_sizes, int n_in,
                              void* d_out, int out_size) {
    (void)in_sizes; (void)n_in; (void)out_size;
    const float* ch1 = (const float*)d_in[0];
    const float* ch2 = (const float*)d_in[1];
    const float* M1  = (const float*)d_in[2];
    const float* M2  = (const float*)d_in[3];
    float* out = (float*)d_out;

    cudaFuncSetAttribute(k_all, cudaFuncAttributeMaxDynamicSharedMemorySize,
                         SMEM_KEYS_BYTES);
    k_all<<<NB, NT, SMEM_KEYS_BYTES>>>(ch1, ch2, M1, M2, out);
}

// round 14
// speedup vs baseline: 1.4811x; 1.0350x over previous
#include <cuda_runtime.h>
#include <float.h>
#include <math.h>

// Problem constants (fixed by setup_inputs)
#define NPTS 8192
#define KNN 16
#define GS 192
#define NCELLS (GS * GS)          // 36864
#define NB 148                    // blocks (1 per SM, all co-resident)
#define NT 1024                   // threads per block (32 warps/SM)
#define NWPB (NT / 32)
#define NWARPS (NB * NWPB)
#define SMEM_KEYS_BYTES (NWPB * 32 * KNN * 8)   // 128 KB

#define FIXP 16777216.0           // 2^24

typedef unsigned long long u64;

// ---------------- scratch (static device globals; no dynamic allocation) ----
__device__ float    g_mx[NPTS], g_my[NPTS];
__device__ int      g_counts[NCELLS], g_qcounts[NCELLS];
__device__ int      g_start[NCELLS + 1];
__device__ int      g_fill[NCELLS], g_qfill[NCELLS];
__device__ int      g_cellof[NPTS], g_qcell[NPTS];
__device__ float4   g_bpt[NPTS];                 // x, y, id_bits, 0
__device__ float2   g_qxy[NPTS];
__device__ int      g_qid[NPTS];
__device__ int      g_r0[NCELLS];                // per-query-cell square radius
__device__ float2   g_nn[NPTS * KNN];            // coords of k-th nearest
__device__ long long g_accum;
__device__ int      g_qnext;
__device__ int      g_done;
__device__ volatile int g_bar_cnt;
__device__ volatile int g_bar_gen;

// Grid-wide barrier. Safe: all NB blocks are co-resident (1 per SM).
__device__ __forceinline__ void gbar() {
    __syncthreads();
    if (threadIdx.x == 0) {
        int gen = g_bar_gen;
        __threadfence();
        int old = atomicAdd((int*)&g_bar_cnt, 1);
        if (old == NB - 1) {
            g_bar_cnt = 0;
            __threadfence();
            g_bar_gen = gen + 1;
        } else {
            while (g_bar_gen == gen) __nanosleep(32);
            __threadfence();
        }
    }
    __syncthreads();
}

// Exclusive scan of NCELLS ints by one NT-thread block (2-pass, 36/thread).
__device__ __forceinline__ void scanN(const int* __restrict__ cnt,
                                      int* __restrict__ outp,
                                      int* __restrict__ outp2,
                                      bool write_total) {
    __shared__ int wsum[NWPB];
    int t = threadIdx.x, lane = t & 31, w = t >> 5;
    const int4* c4 = (const int4*)cnt;
    const int PT = NCELLS / NT / 4;      // int4s per thread = 9
    int tot = 0;
#pragma unroll
    for (int j = 0; j < PT; j++) {
        int4 a = c4[t * PT + j];
        tot += a.x + a.y + a.z + a.w;
    }
    int x = tot;
#pragma unroll
    for (int o = 1; o < 32; o <<= 1) {
        int u = __shfl_up_sync(0xFFFFFFFFu, x, o);
        if (lane >= o) x += u;
    }
    if (lane == 31) wsum[w] = x;
    __syncthreads();
    if (w == 0) {
        int y = wsum[lane];
#pragma unroll
        for (int o = 1; o < 32; o <<= 1) {
            int u = __shfl_up_sync(0xFFFFFFFFu, y, o);
            if (lane >= o) y += u;
        }
        wsum[lane] = y;
    }
    __syncthreads();
    int run = x - tot + (w > 0 ? wsum[w - 1] : 0);
#pragma unroll
    for (int j = 0; j < PT; j++) {
        int4 a = c4[t * PT + j];
        int4 o;
        o.x = run; o.y = run + a.x; o.z = o.y + a.y; o.w = o.z + a.z;
        run = o.w + a.w;
        ((int4*)outp)[t * PT + j] = o;
        ((int4*)outp2)[t * PT + j] = o;
    }
    if (write_total && t == NT - 1) outp[NCELLS] = run;
}

// Warp-collective count of points in clamped square radius r around (cx,cy).
__device__ __forceinline__ int count_square(int qcx, int qcy, int r, int lane) {
    int xl = max(0, qcx - r), xr = min(GS - 1, qcx + r);
    int yl = max(0, qcy - r), yh = min(GS - 1, qcy + r);
    int c = 0;
    for (int y = yl + lane; y <= yh; y += 32)
        c += g_start[y * GS + xr + 1] - g_start[y * GS + xl];
    return __reduce_add_sync(0xFFFFFFFFu, c);
}

// ---------------- the single persistent kernel ------------------------------

__global__ void __launch_bounds__(NT, 1) k_all(const float* __restrict__ ch1,
                                               const float* __restrict__ ch2,
                                               const float* __restrict__ M1,
                                               const float* __restrict__ M2,
                                               float* __restrict__ out) {
    extern __shared__ u64 s_keys[];     // interleaved: [(w*KNN + s)*32 + lane]
    __shared__ float s_red[4 * NWPB];
    __shared__ float s_sum[NWPB];
    __shared__ float s_bbox[4];

    int b = blockIdx.x, t = threadIdx.x;
    int lane = t & 31, w = t >> 5;
    int g = b * NT + t;
    int s0 = (int)(((long long)b * NPTS) / NB);
    int e0 = (int)(((long long)(b + 1) * NPTS) / NB);

    // ===== Phase A: zero counts, poly map (slice writes) + LOCAL full bbox ==
    // Every block scans all NPTS points and derives an identical bbox in
    // registers/smem (deterministic: same inputs, same op order). No global
    // reduction, no extra barrier.
    {
        const int NQ4 = NCELLS / 4;      // 9216
        if (g < NQ4) ((int4*)g_counts)[g] = make_int4(0, 0, 0, 0);
        else if (g < 2 * NQ4) ((int4*)g_qcounts)[g - NQ4] = make_int4(0, 0, 0, 0);
        if (g == 0) { g_accum = 0; g_qnext = 0; g_done = 0; }

        float m10 = M1[0], m11 = M1[1], m12 = M1[2], m13 = M1[3];
        float m20 = M2[0], m21 = M2[1], m22 = M2[2], m23 = M2[3];
        float mnx = FLT_MAX, mxx = -FLT_MAX, mny = FLT_MAX, mxy = -FLT_MAX;
#pragma unroll
        for (int k = 0; k < NPTS / NT; k++) {
            int i = t + k * NT;
            float2 c = ((const float2*)ch2)[i];
            float y1 = m10 + m11 * c.y + m12 * c.x + m13 * c.x * c.y;
            float y2 = m20 + m21 * c.y + m22 * c.x + m23 * c.x * c.y;
            if (i >= s0 && i < e0) { g_mx[i] = y1; g_my[i] = y2; }
            mnx = fminf(mnx, y1); mxx = fmaxf(mxx, y1);
            mny = fminf(mny, y2); mxy = fmaxf(mxy, y2);
        }
#pragma unroll
        for (int o = 16; o > 0; o >>= 1) {
            mnx = fminf(mnx, __shfl_xor_sync(0xFFFFFFFFu, mnx, o));
            mxx = fmaxf(mxx, __shfl_xor_sync(0xFFFFFFFFu, mxx, o));
            mny = fminf(mny, __shfl_xor_sync(0xFFFFFFFFu, mny, o));
            mxy = fmaxf(mxy, __shfl_xor_sync(0xFFFFFFFFu, mxy, o));
        }
        if (lane == 0) {
            s_red[w] = mnx; s_red[NWPB + w] = mxx;
            s_red[2 * NWPB + w] = mny; s_red[3 * NWPB + w] = mxy;
        }
        __syncthreads();
        if (w == 0) {
            float A = s_red[lane];
            float B = s_red[NWPB + lane];
            float C = s_red[2 * NWPB + lane];
            float D = s_red[3 * NWPB + lane];
#pragma unroll
            for (int o = 16; o > 0; o >>= 1) {
                A = fminf(A, __shfl_xor_sync(0xFFFFFFFFu, A, o));
                B = fmaxf(B, __shfl_xor_sync(0xFFFFFFFFu, B, o));
                C = fminf(C, __shfl_xor_sync(0xFFFFFFFFu, C, o));
                D = fmaxf(D, __shfl_xor_sync(0xFFFFFFFFu, D, o));
            }
            if (lane == 0) {
                s_bbox[0] = A; s_bbox[1] = B; s_bbox[2] = C; s_bbox[3] = D;
            }
        }
        __syncthreads();
    }
    gbar();

    // ===== Phase B: bin points + queries ====================================
    float minx = s_bbox[0], maxx = s_bbox[1];
    float miny = s_bbox[2], maxy = s_bbox[3];
    float rxr = fmaxf(maxx - minx, 1e-20f);
    float ryr = fmaxf(maxy - miny, 1e-20f);
    float ivx = (float)GS / rxr, ivy = (float)GS / ryr;
    float hx = rxr / (float)GS, hy = ryr / (float)GS;

    for (int i = s0 + t; i < e0; i += NT) {
        int cx = min(GS - 1, max(0, (int)((g_mx[i] - minx) * ivx)));
        int cy = min(GS - 1, max(0, (int)((g_my[i] - miny) * ivy)));
        int c = cy * GS + cx;
        g_cellof[i] = c;
        atomicAdd(&g_counts[c], 1);
        float2 q = ((const float2*)ch1)[i];
        int qcx = min(GS - 1, max(0, (int)((q.x - minx) * ivx)));
        int qcy = min(GS - 1, max(0, (int)((q.y - miny) * ivy)));
        int qc = qcy * GS + qcx;
        g_qcell[i] = qc;
        atomicAdd(&g_qcounts[qc], 1);
    }
    gbar();

    // ===== Phase C: scans (blocks 0 and 1 in parallel) ======================
    if (b == 0) scanN(g_counts, g_start, g_fill, true);
    else if (b == 1) scanN(g_qcounts, g_qfill, g_qfill, false);
    gbar();

    // ===== Phase D: scatter + per-cell r0 precompute ========================
    for (int i = s0 + t; i < e0; i += NT) {
        int c = g_cellof[i];
        int p = atomicAdd(&g_fill[c], 1);
        g_bpt[p] = make_float4(g_mx[i], g_my[i], __int_as_float(i), 0.0f);
        int qc = g_qcell[i];
        int pq = atomicAdd(&g_qfill[qc], 1);
        g_qxy[pq] = ((const float2*)ch1)[i];
        g_qid[pq] = i;
    }
    // E0: exact minimal r0 per occupied query cell, lanes 0-15 test r=1..16
    {
        int wg = b * NWPB + w;
        for (int cell = wg; cell < NCELLS; cell += NWARPS) {
            if (g_qcounts[cell] == 0) continue;
            int qcx = cell % GS, qcy = cell / GS;
            int cnt = 0;
            if (lane < 16) {
                int rr = lane + 1;
                int xl = max(0, qcx - rr), xr = min(GS - 1, qcx + rr);
                int yl = max(0, qcy - rr), yh = min(GS - 1, qcy + rr);
                for (int y = yl; y <= yh; ++y)
                    cnt += g_start[y * GS + xr + 1] - g_start[y * GS + xl];
            }
            unsigned ball = __ballot_sync(0xFFFFFFFFu, (lane < 16) && (cnt >= KNN));
            int r0v;
            if (ball) {
                r0v = __ffs(ball);               // lane idx + 1 == radius
            } else {                             // sparse edge cell: expand
                int lo = 16, hi = 24;
                int c2 = count_square(qcx, qcy, hi, lane);
                while (c2 < KNN && hi < GS) {
                    lo = hi; hi = min(GS, hi + (hi >> 1));
                    c2 = count_square(qcx, qcy, hi, lane);
                }
                while (hi - lo > 1) {
                    int mid = (lo + hi) >> 1;
                    if (count_square(qcx, qcy, mid, lane) >= KNN) hi = mid;
                    else lo = mid;
                }
                r0v = hi;
            }
            if (lane == 0) g_r0[cell] = r0v;
        }
    }
    gbar();

    // ===== Phase E: dynamic warp-per-query exact 16-NN ======================
    {
        for (;;) {
            int q;
            if (lane == 0) q = atomicAdd(&g_qnext, 1);
            q = __shfl_sync(0xFFFFFFFFu, q, 0);
            if (q >= NPTS) break;

            float2 Q = g_qxy[q];
            float qx = Q.x, qy = Q.y;
            int orig = g_qid[q];
            int qcx = min(GS - 1, max(0, (int)((qx - minx) * ivx)));
            int qcy = min(GS - 1, max(0, (int)((qy - miny) * ivy)));
            int r0 = g_r0[qcy * GS + qcx];

            // D2 = far-corner bound of the r0-square around the cell.
            float dxf = fmaxf(qx - (minx + (float)(qcx - r0) * hx),
                              (minx + (float)(qcx + r0 + 1) * hx) - qx) + 1e-4f;
            float dyf = fmaxf(qy - (miny + (float)(qcy - r0) * hy),
                              (miny + (float)(qcy + r0 + 1) * hy) - qy) + 1e-4f;
            float D2 = dxf * dxf + dyf * dyf;
            float Dr = sqrtf(D2);

            int by0 = max(0, (int)floorf((qy - Dr - miny) * ivy) - 1);
            int by1 = min(GS - 1, (int)floorf((qy + Dr - miny) * ivy) + 1);

            u64 keys[KNN];
#pragma unroll
            for (int s = 0; s < KNN; s++) keys[s] = 0xFFFFFFFFFFFFFFFFull;

            for (int ybase = by0; ybase <= by1; ybase += 32) {
                int y = ybase + lane;
                int rs = 0, len = 0;
                if (y <= by1) {
                    // disc-shaped span: row y only needs |px-qx| <= dxmax
                    float ylo = miny + (float)y * hy, yhi = ylo + hy;
                    float dye = fmaxf(0.0f, fmaxf(ylo - qy, qy - yhi));
                    dye = fmaxf(dye - 1e-4f, 0.0f);
                    float rem = D2 - dye * dye;
                    if (rem > 0.0f) {
                        float dxm = sqrtf(rem);
                        int x0 = max(0, (int)floorf((qx - dxm - minx) * ivx) - 1);
                        int x1 = min(GS - 1, (int)floorf((qx + dxm - minx) * ivx) + 1);
                        rs = g_start[y * GS + x0];
                        len = g_start[y * GS + x1 + 1] - rs;
                    }
                }
                int pre = len;
#pragma unroll
                for (int o = 1; o < 32; o <<= 1) {
                    int u = __shfl_up_sync(0xFFFFFFFFu, pre, o);
                    if (lane >= o) pre += u;
                }
                int T = __shfl_sync(0xFFFFFFFFu, pre, 31);
                int excl = pre - len;

                for (int base = 0; base < T; base += 32) {
                    int idx = base + lane;
                    bool act = idx < T;
                    // find row j = max{j : excl_j <= idx} via shfl binary search
                    int jlo = 0;
#pragma unroll
                    for (int s = 16; s > 0; s >>= 1) {
                        int jm = jlo + s;
                        int ev = __shfl_sync(0xFFFFFFFFu, excl, min(jm, 31));
                        if (jm <= 31 && ev <= idx) jlo = jm;
                    }
                    int rrs = __shfl_sync(0xFFFFFFFFu, rs, jlo);
                    int rex = __shfl_sync(0xFFFFFFFFu, excl, jlo);
                    if (act) {
                        int tt = rrs + (idx - rex);
                        float4 p = g_bpt[tt];
                        float dx = qx - p.x;
                        float dy = qy - p.y;
                        float d = __fadd_rn(__fmul_rn(dx, dx), __fmul_rn(dy, dy));
                        if (d <= D2) {
                            u64 key = ((u64)__float_as_uint(d) << 32) |
                                      (unsigned)__float_as_int(p.z);
                            if (key < keys[KNN - 1]) {
                                keys[KNN - 1] = key;
#pragma unroll
                                for (int s = KNN - 1; s > 0; --s) {
                                    if (keys[s] < keys[s - 1]) {
                                        u64 tk = keys[s];
                                        keys[s] = keys[s - 1];
                                        keys[s - 1] = tk;
                                    }
                                }
                            }
                        }
                    }
                }
            }

            // exact sorted warp merge: interleaved smem + 2xREDUX per round.
            // Lane k captures round-k's winner id; lanes 0-15 then write the
            // winners' COORDS to g_nn (16 parallel scattered loads, once).
#pragma unroll
            for (int s = 0; s < KNN; s++)
                s_keys[(w * KNN + s) * 32 + lane] = keys[s];
            int head = 0;
            int mywin = 0;
            u64 cur = keys[0];
#pragma unroll 1
            for (int k = 0; k < KNN; k++) {
                unsigned hi = (unsigned)(cur >> 32);
                unsigned m = __reduce_min_sync(0xFFFFFFFFu, hi);
                unsigned lov = (hi == m) ? (unsigned)cur : 0xFFFFFFFFu;
                unsigned ml = __reduce_min_sync(0xFFFFFFFFu, lov);
                if (lane == k) mywin = (int)ml;
                if (hi == m && (unsigned)cur == ml) {
                    head++;
                    cur = (head < KNN) ? s_keys[(w * KNN + head) * 32 + lane]
                                       : 0xFFFFFFFFFFFFFFFFull;
                }
            }
            if (lane < KNN)
                g_nn[orig * KNN + lane] = make_float2(g_mx[mywin], g_my[mywin]);
        }
    }
    gbar();

    // ===== Phase F: scrambled gather + KL log-sum + last-block finale =======
    {
        float part = 0.0f;
        for (int n = s0 + t; n < e0; n += NT) {
            float2 qp = ((const float2*)ch1)[n];
            float qx = qp.x, qy = qp.y;
            int qq = n >> 4, col = n & 15;
            const float inv_s4 = 1.0f / 2.25f;  // 1 / sigma2^2, sigma2 = 1.5
            float acc = 0.0f;
#pragma unroll
            for (int k = 0; k < 16; k++) {
                float2 c = g_nn[(k * 512 + qq) * KNN + col];
                float dx = qx - c.x;
                float dy = qy - c.y;
                float D = 0.5f * (__fmul_rn(dx, dx) * inv_s4 + __fmul_rn(dy, dy) * inv_s4);
                acc += __expf(-D);
            }
            float expD = acc * (1.0f / (float)NPTS);
            part += (expD != 0.0f) ? __logf(expD) : 0.0f;
        }
#pragma unroll
        for (int o = 16; o > 0; o >>= 1)
            part += __shfl_xor_sync(0xFFFFFFFFu, part, o);
        if (lane == 0) s_sum[w] = part;
        __syncthreads();
        if (w == 0) {
            float v = s_sum[lane];
#pragma unroll
            for (int o = 16; o > 0; o >>= 1)
                v += __shfl_xor_sync(0xFFFFFFFFu, v, o);
            if (lane == 0) {
                long long fv = __double2ll_rn((double)v * FIXP);
                atomicAdd((unsigned long long*)&g_accum, (unsigned long long)fv);
                __threadfence();
                int old = atomicAdd(&g_done, 1);
                if (old == NB - 1) {
                    u64 tot = atomicAdd((unsigned long long*)&g_accum, 0ull);
                    out[0] = (float)(-((double)(long long)tot / FIXP));
                }
            }
        }
    }
}

// ---------------- launch ----------------------------------------------------

extern "C" void kernel_launch(void* const* d_in, const int* in_sizes, int n_in,
                              void* d_out, int out_size) {
    (void)in_sizes; (void)n_in; (void)out_size;
    const float* ch1 = (const float*)d_in[0];
    const float* ch2 = (const float*)d_in[1];
    const float* M1  = (const float*)d_in[2];
    const float* M2  = (const float*)d_in[3];
    float* out = (float*)d_out;

    cudaFuncSetAttribute(k_all, cudaFuncAttributeMaxDynamicSharedMemorySize,
                         SMEM_KEYS_BYTES);
    k_all<<<NB, NT, SMEM_KEYS_BYTES>>>(ch1, ch2, M1, M2, out);
}